// round 7
// baseline (speedup 1.0000x reference)
#include <cuda_runtime.h>
#include <cstdint>

// Max-unpool scatter, deterministic last-index-wins (matches reference).
//
// Round-7: R5 topology + L2 dirty-line DISCARD.
//   The winner scratch is write-twice/read-once per replay and its contents
//   are meaningless after compact. Without intervention, ~103MB of dirty L2
//   lines get written back to HBM every replay (seen as DRAM=35% on the zero
//   kernel). compact issues discard.global.L2 on each consumed scratch line:
//   invalidate WITHOUT writeback -> scratch lives entirely in L2.
//   Z: zero scratch, 4x uint4/thread, block-strided (coalesced)
//   S: atomicMax(scr[pos[i]], i+1), 8 atomics/thread, pos via __ldcs
//   C: 8 outputs/thread, block-strided; scratch __ldcs then DISCARD;
//      x __ldg (L2 reuse), out __stcs (write-once)

#define N_OUT_CONST 25690112  // 32*112*112*64

__device__ unsigned int g_winner[N_OUT_CONST];

// Each block owns 4*T consecutive uint4 slots; thread t stores slots
// base+t+k*T, k=0..3 (warp-coalesced full 128B lines, ILP=4).
__global__ void zero_scratch_kernel() {
    const int T = blockDim.x;
    int base = blockIdx.x * (T * 4) + threadIdx.x;
    uint4* p = reinterpret_cast<uint4*>(g_winner);
    uint4 z = make_uint4(0u, 0u, 0u, 0u);
    p[base + 0 * T] = z;
    p[base + 1 * T] = z;
    p[base + 2 * T] = z;
    p[base + 3 * T] = z;
}

// n8 = n/8 threads, each loads 2 int4 of pos and issues 8 atomics.
__global__ void scatter_kernel(const int4* __restrict__ p4, int n8) {
    int t = blockIdx.x * blockDim.x + threadIdx.x;
    if (t >= n8) return;
    int4 a = __ldcs(&p4[2 * t + 0]);
    int4 b = __ldcs(&p4[2 * t + 1]);
    unsigned int base = (unsigned int)(t * 8);
    atomicMax(&g_winner[a.x], base + 1u);
    atomicMax(&g_winner[a.y], base + 2u);
    atomicMax(&g_winner[a.z], base + 3u);
    atomicMax(&g_winner[a.w], base + 4u);
    atomicMax(&g_winner[b.x], base + 5u);
    atomicMax(&g_winner[b.y], base + 6u);
    atomicMax(&g_winner[b.z], base + 7u);
    atomicMax(&g_winner[b.w], base + 8u);
}

// Each block owns 2*T consecutive uint4 slots (8*T outputs); thread t handles
// slots base+t and base+t+T. After the x-gathers have consumed the winner
// registers (warp scoreboard drained -> scratch loads complete for ALL lanes),
// one lane per 128B line discards it from L2 (invalidate, no writeback).
__global__ void compact_kernel(float* __restrict__ out,
                               const float* __restrict__ x) {
    const int T = blockDim.x;
    int base = blockIdx.x * (T * 2) + threadIdx.x;

    const uint4* __restrict__ sp = reinterpret_cast<const uint4*>(g_winner);
    float4* __restrict__ op = reinterpret_cast<float4*>(out);

    uint4 w0 = __ldcs(&sp[base + 0 * T]);
    uint4 w1 = __ldcs(&sp[base + 1 * T]);

    float4 o0, o1;
    o0.x = w0.x ? __ldg(&x[w0.x - 1u]) : 0.0f;
    o0.y = w0.y ? __ldg(&x[w0.y - 1u]) : 0.0f;
    o0.z = w0.z ? __ldg(&x[w0.z - 1u]) : 0.0f;
    o0.w = w0.w ? __ldg(&x[w0.w - 1u]) : 0.0f;
    o1.x = w1.x ? __ldg(&x[w1.x - 1u]) : 0.0f;
    o1.y = w1.y ? __ldg(&x[w1.y - 1u]) : 0.0f;
    o1.z = w1.z ? __ldg(&x[w1.z - 1u]) : 0.0f;
    o1.w = w1.w ? __ldg(&x[w1.w - 1u]) : 0.0f;

    // Discard consumed scratch lines: scratch data never reaches DRAM.
    // Lines are warp-exclusive; x-gather issue above already forced the
    // warp to wait for every lane's scratch load.
    if ((threadIdx.x & 7) == 0) {
        asm volatile("discard.global.L2 [%0], 128;"
                     :: "l"(sp + base + 0 * T) : "memory");
        asm volatile("discard.global.L2 [%0], 128;"
                     :: "l"(sp + base + 1 * T) : "memory");
    }

    __stcs(&op[base + 0 * T], o0);
    __stcs(&op[base + 1 * T], o1);
}

extern "C" void kernel_launch(void* const* d_in, const int* in_sizes, int n_in,
                              void* d_out, int out_size) {
    const float* x = reinterpret_cast<const float*>(d_in[0]);
    const int* pos = reinterpret_cast<const int*>(d_in[1]);
    float* out     = reinterpret_cast<float*>(d_out);

    int n = in_sizes[0];             // 6,422,528 (divisible by 8)
    int n8 = n / 8;
    int count4 = out_size / 4;       // 6,422,528 uint4 slots

    const int T = 256;
    // count4 = 6272*1024: divisible by both 4*T and 2*T -> exact grids.
    const int ZG = count4 / (4 * T);
    const int SG = (n8 + T - 1) / T;
    const int CG = count4 / (2 * T);

    // Z: zero the winner scratch (heats it in L2 right before the atomics).
    zero_scratch_kernel<<<ZG, T>>>();

    // S: deterministic last-index-wins via 32-bit atomicMax, 8/thread.
    scatter_kernel<<<SG, T>>>(reinterpret_cast<const int4*>(pos), n8);

    // C: gather winners' values, zero-fill empties, discard scratch lines,
    //    stream out.
    compact_kernel<<<CG, T>>>(out, x);
}